// round 2
// baseline (speedup 1.0000x reference)
#include <cuda_runtime.h>
#include <math.h>

#define B_  4
#define N_  2048
#define DIM_ 1024
#define H_  16
#define DH_ 64

// Scratch (allocation-free: __device__ globals)
__device__ float g_q[B_ * H_ * N_ * DH_];
__device__ float g_k[B_ * H_ * N_ * DH_];
__device__ float g_v[B_ * H_ * N_ * DH_];
__device__ float g_ctx[B_ * N_ * DIM_];

// ---------------------------------------------------------------------------
// Tiled SGEMM: C[M,Nout] = A[M,K] @ W[Nout,K]^T + bias
// BM=BN=128, BK=8, 256 threads, 8x8 per thread.
// QKV=true: A is x; epilogue scatters q/k/v into [B,H,N,DH] and adds noise to q.
// QKV=false: A is g_ctx; epilogue writes C (d_out) with bias.
// ---------------------------------------------------------------------------
template <bool QKV>
__global__ __launch_bounds__(256) void gemm_nt(
    const float* __restrict__ A, const float* __restrict__ W,
    const float* __restrict__ bias, float* __restrict__ C,
    int M, int Nout, int K,
    const float* __restrict__ eps, const float* __restrict__ temp)
{
    __shared__ float As[8][128];
    __shared__ float Bs[8][128];

    const int tid = threadIdx.x;
    const int tx = tid & 15;
    const int ty = tid >> 4;
    const int m0 = blockIdx.y * 128;
    const int n0 = blockIdx.x * 128;

    const int lr = tid >> 1;        // 0..127
    const int ls = (tid & 1) * 4;   // 0 or 4

    const float* Aeff = QKV ? A : (const float*)g_ctx;
    const float* Aptr = Aeff + (size_t)(m0 + lr) * K + ls;
    const float* Wptr = W    + (size_t)(n0 + lr) * K + ls;

    float acc[8][8];
#pragma unroll
    for (int i = 0; i < 8; ++i)
#pragma unroll
        for (int j = 0; j < 8; ++j) acc[i][j] = 0.f;

    for (int k0 = 0; k0 < K; k0 += 8) {
        float4 a4 = *(const float4*)(Aptr + k0);
        float4 b4 = *(const float4*)(Wptr + k0);
        __syncthreads();
        As[ls + 0][lr] = a4.x; As[ls + 1][lr] = a4.y;
        As[ls + 2][lr] = a4.z; As[ls + 3][lr] = a4.w;
        Bs[ls + 0][lr] = b4.x; Bs[ls + 1][lr] = b4.y;
        Bs[ls + 2][lr] = b4.z; Bs[ls + 3][lr] = b4.w;
        __syncthreads();

#pragma unroll
        for (int kk = 0; kk < 8; ++kk) {
            float4 af0 = *(const float4*)&As[kk][ty * 8];
            float4 af1 = *(const float4*)&As[kk][ty * 8 + 4];
            float4 bf0 = *(const float4*)&Bs[kk][tx * 8];
            float4 bf1 = *(const float4*)&Bs[kk][tx * 8 + 4];
            float a_[8] = {af0.x, af0.y, af0.z, af0.w, af1.x, af1.y, af1.z, af1.w};
            float b_[8] = {bf0.x, bf0.y, bf0.z, bf0.w, bf1.x, bf1.y, bf1.z, bf1.w};
#pragma unroll
            for (int i = 0; i < 8; ++i)
#pragma unroll
                for (int j = 0; j < 8; ++j)
                    acc[i][j] = fmaf(a_[i], b_[j], acc[i][j]);
        }
    }

    float sig = 0.f;
    if (QKV) sig = 1.f / (1.f + __expf(-temp[0]));

#pragma unroll
    for (int i = 0; i < 8; ++i) {
        const int m = m0 + ty * 8 + i;
        const int bb = m >> 11;        // /N_
        const int nn = m & (N_ - 1);
#pragma unroll
        for (int j = 0; j < 8; ++j) {
            const int col = n0 + tx * 8 + j;
            const float val = acc[i][j] + bias[col];
            if (QKV) {
                const int which = col >> 10;       // 0=q 1=k 2=v
                const int rem = col & 1023;
                const int h = rem >> 6;
                const int d = rem & 63;
                const size_t idx = ((size_t)((bb * H_ + h) * N_) + nn) * DH_ + d;
                if (which == 0)      g_q[idx] = val + eps[idx] * sig;
                else if (which == 1) g_k[idx] = val;
                else                 g_v[idx] = val;
            } else {
                C[(size_t)m * Nout + col] = val;
            }
        }
    }
}

// ---------------------------------------------------------------------------
// Flash-attention: one block per (b*h, 64-query tile). 256 threads.
// Q tile (pre-scaled) resident in smem; stream 64-key tiles; online softmax.
// Ks buffer is reused to hold P during the PV stage (exactly 48KB smem).
// ---------------------------------------------------------------------------
#define PV_STEP(comp, vrow)                                                     \
    {                                                                           \
        float4 vv = *(const float4*)(Vs + (vrow) * 64 + tx * 4);                \
        o[0][0] = fmaf(pa.comp, vv.x, o[0][0]); o[0][1] = fmaf(pa.comp, vv.y, o[0][1]); \
        o[0][2] = fmaf(pa.comp, vv.z, o[0][2]); o[0][3] = fmaf(pa.comp, vv.w, o[0][3]); \
        o[1][0] = fmaf(pb.comp, vv.x, o[1][0]); o[1][1] = fmaf(pb.comp, vv.y, o[1][1]); \
        o[1][2] = fmaf(pb.comp, vv.z, o[1][2]); o[1][3] = fmaf(pb.comp, vv.w, o[1][3]); \
        o[2][0] = fmaf(pc.comp, vv.x, o[2][0]); o[2][1] = fmaf(pc.comp, vv.y, o[2][1]); \
        o[2][2] = fmaf(pc.comp, vv.z, o[2][2]); o[2][3] = fmaf(pc.comp, vv.w, o[2][3]); \
        o[3][0] = fmaf(pd.comp, vv.x, o[3][0]); o[3][1] = fmaf(pd.comp, vv.y, o[3][1]); \
        o[3][2] = fmaf(pd.comp, vv.z, o[3][2]); o[3][3] = fmaf(pd.comp, vv.w, o[3][3]); \
    }

__global__ __launch_bounds__(256) void attn_kernel()
{
    __shared__ float Qs[64 * 64];
    __shared__ float Ks[64 * 64];   // reused as P after softmax
    __shared__ float Vs[64 * 64];

    const int bh = blockIdx.x;
    const int b = bh >> 4;
    const int h = bh & 15;
    const int q0 = blockIdx.y * 64;
    const int tid = threadIdx.x;
    const int tx = tid & 15;
    const int ty = tid >> 4;

    const size_t head_off = (size_t)(b * H_ + h) * N_ * DH_;
    const float* qbase = g_q + head_off;
    const float* kbase = g_k + head_off;
    const float* vbase = g_v + head_off;

    const float scale = 0.125f;   // 1/sqrt(64)

    // Load Q tile (scaled)
    for (int v = tid; v < 64 * 16; v += 256) {
        const int r = v >> 4, s = v & 15;
        float4 t4 = *(const float4*)(qbase + (size_t)(q0 + r) * DH_ + s * 4);
        t4.x *= scale; t4.y *= scale; t4.z *= scale; t4.w *= scale;
        *(float4*)(Qs + r * 64 + s * 4) = t4;
    }

    float o[4][4];
#pragma unroll
    for (int i = 0; i < 4; ++i)
#pragma unroll
        for (int j = 0; j < 4; ++j) o[i][j] = 0.f;
    float mi[4] = {-INFINITY, -INFINITY, -INFINITY, -INFINITY};
    float li[4] = {0.f, 0.f, 0.f, 0.f};

    for (int kt = 0; kt < N_ / 64; ++kt) {
        const int k0 = kt * 64;
        __syncthreads();  // prior PV readers of Ks/Vs done (also covers Q store on iter 0)
        for (int v = tid; v < 64 * 16; v += 256) {
            const int r = v >> 4, s = v & 15;
            *(float4*)(Ks + r * 64 + s * 4) =
                *(const float4*)(kbase + (size_t)(k0 + r) * DH_ + s * 4);
            *(float4*)(Vs + r * 64 + s * 4) =
                *(const float4*)(vbase + (size_t)(k0 + r) * DH_ + s * 4);
        }
        __syncthreads();

        // S = Q @ K^T  (4x4 per thread)
        float s_[4][4];
#pragma unroll
        for (int i = 0; i < 4; ++i)
#pragma unroll
            for (int j = 0; j < 4; ++j) s_[i][j] = 0.f;

#pragma unroll
        for (int d4 = 0; d4 < 16; ++d4) {
            float4 q4[4], k4[4];
#pragma unroll
            for (int i = 0; i < 4; ++i)
                q4[i] = *(const float4*)(Qs + (ty * 4 + i) * 64 + d4 * 4);
#pragma unroll
            for (int j = 0; j < 4; ++j)
                k4[j] = *(const float4*)(Ks + (tx * 4 + j) * 64 + d4 * 4);
#pragma unroll
            for (int i = 0; i < 4; ++i)
#pragma unroll
                for (int j = 0; j < 4; ++j) {
                    s_[i][j] = fmaf(q4[i].x, k4[j].x, s_[i][j]);
                    s_[i][j] = fmaf(q4[i].y, k4[j].y, s_[i][j]);
                    s_[i][j] = fmaf(q4[i].z, k4[j].z, s_[i][j]);
                    s_[i][j] = fmaf(q4[i].w, k4[j].w, s_[i][j]);
                }
        }

        // Online softmax update (row reduce across the 16 tx lanes)
        float p[4][4];
#pragma unroll
        for (int i = 0; i < 4; ++i) {
            float mx = fmaxf(fmaxf(s_[i][0], s_[i][1]), fmaxf(s_[i][2], s_[i][3]));
#pragma unroll
            for (int off = 1; off < 16; off <<= 1)
                mx = fmaxf(mx, __shfl_xor_sync(0xffffffffu, mx, off));
            const float nm = fmaxf(mi[i], mx);
            const float corr = __expf(mi[i] - nm);
            mi[i] = nm;
            float rs = 0.f;
#pragma unroll
            for (int j = 0; j < 4; ++j) {
                p[i][j] = __expf(s_[i][j] - nm);
                rs += p[i][j];
            }
#pragma unroll
            for (int off = 1; off < 16; off <<= 1)
                rs += __shfl_xor_sync(0xffffffffu, rs, off);
            li[i] = li[i] * corr + rs;
#pragma unroll
            for (int j = 0; j < 4; ++j) o[i][j] *= corr;
        }

        __syncthreads();  // all S reads of Ks complete
#pragma unroll
        for (int i = 0; i < 4; ++i)
#pragma unroll
            for (int j = 0; j < 4; ++j)
                Ks[(ty * 4 + i) * 64 + tx * 4 + j] = p[i][j];
        __syncthreads();

        // O += P @ V
#pragma unroll
        for (int c4 = 0; c4 < 16; ++c4) {
            float4 pa = *(const float4*)(Ks + (ty * 4 + 0) * 64 + c4 * 4);
            float4 pb = *(const float4*)(Ks + (ty * 4 + 1) * 64 + c4 * 4);
            float4 pc = *(const float4*)(Ks + (ty * 4 + 2) * 64 + c4 * 4);
            float4 pd = *(const float4*)(Ks + (ty * 4 + 3) * 64 + c4 * 4);
            PV_STEP(x, c4 * 4 + 0);
            PV_STEP(y, c4 * 4 + 1);
            PV_STEP(z, c4 * 4 + 2);
            PV_STEP(w, c4 * 4 + 3);
        }
    }

    // Normalize and write context in [B, N, DIM] layout
#pragma unroll
    for (int i = 0; i < 4; ++i) {
        const float inv = 1.f / li[i];
        const int m = b * N_ + q0 + ty * 4 + i;
        float4 r;
        r.x = o[i][0] * inv; r.y = o[i][1] * inv;
        r.z = o[i][2] * inv; r.w = o[i][3] * inv;
        *(float4*)(g_ctx + (size_t)m * DIM_ + h * DH_ + tx * 4) = r;
    }
}

// ---------------------------------------------------------------------------
extern "C" void kernel_launch(void* const* d_in, const int* in_sizes, int n_in,
                              void* d_out, int out_size)
{
    const float* x      = (const float*)d_in[0];
    const float* qkv_w  = (const float*)d_in[1];
    const float* qkv_b  = (const float*)d_in[2];
    const float* proj_w = (const float*)d_in[3];
    const float* proj_b = (const float*)d_in[4];
    const float* temp   = (const float*)d_in[5];
    const float* eps    = (const float*)d_in[6];
    float* out = (float*)d_out;

    const int M = B_ * N_;  // 8192

    dim3 gA(3 * DIM_ / 128, M / 128);   // (24, 64)
    gemm_nt<true><<<gA, 256>>>(x, qkv_w, qkv_b, nullptr, M, 3 * DIM_, DIM_, eps, temp);

    dim3 gAtt(B_ * H_, N_ / 64);        // (64, 32)
    attn_kernel<<<gAtt, 256>>>();

    dim3 gC(DIM_ / 128, M / 128);       // (8, 64)
    gemm_nt<false><<<gC, 256>>>(nullptr, proj_w, proj_b, out, M, DIM_, DIM_, nullptr, nullptr);
}

// round 4
// speedup vs baseline: 4.4179x; 4.4179x over previous
#include <cuda_runtime.h>
#include <math.h>
#include <stdint.h>

#define B_   4
#define N_   2048
#define DIM_ 1024
#define H_   16
#define DH_  64

// Scratch (allocation-free: __device__ globals)
__device__ float g_q[B_ * H_ * N_ * DH_];
__device__ float g_k[B_ * H_ * N_ * DH_];
__device__ float g_v[B_ * H_ * N_ * DH_];
__device__ float g_ctx[B_ * N_ * DIM_];

__device__ __forceinline__ float ftf32(float x) {
    uint32_t u;
    asm("cvt.rna.tf32.f32 %0, %1;" : "=r"(u) : "f"(x));
    return __uint_as_float(u);
}

__device__ __forceinline__ void mma_tf32(float c[4], const uint32_t a[4], const uint32_t b[2]) {
    asm volatile(
        "mma.sync.aligned.m16n8k8.row.col.f32.tf32.tf32.f32 "
        "{%0,%1,%2,%3}, {%4,%5,%6,%7}, {%8,%9}, {%0,%1,%2,%3};\n"
        : "+f"(c[0]), "+f"(c[1]), "+f"(c[2]), "+f"(c[3])
        : "r"(a[0]), "r"(a[1]), "r"(a[2]), "r"(a[3]), "r"(b[0]), "r"(b[1]));
}

// ---------------------------------------------------------------------------
// tf32 tensor-core GEMM: C[M,Nout] = A[M,K] @ W[Nout,K]^T + bias
// Block 128x128, BK=16, 8 warps (2x4), warp tile 64x32, double-buffered smem.
// QKV=true: A=x, epilogue scatters q/k/v ([B,H,N,DH]) with noise on q.
// QKV=false: A=g_ctx, epilogue writes C with bias.
// ---------------------------------------------------------------------------
template <bool QKV>
__global__ __launch_bounds__(256) void gemm_tc(
    const float* __restrict__ Ain, const float* __restrict__ W,
    const float* __restrict__ bias, float* __restrict__ C,
    int Nout, int K,
    const float* __restrict__ eps, const float* __restrict__ temp)
{
    __shared__ float As[2][128 * 20];   // [m][k], stride 20 -> conflict-free frags
    __shared__ float Bs[2][128 * 20];   // [n][k]

    const int tid  = threadIdx.x;
    const int wid  = tid >> 5;
    const int lane = tid & 31;
    const int gid  = lane >> 2;   // 0..7
    const int tg   = lane & 3;    // 0..3
    const int wm   = wid & 1;     // 0..1 -> 64 rows
    const int wn   = wid >> 1;    // 0..3 -> 32 cols
    const int m0   = blockIdx.y * 128;
    const int n0   = blockIdx.x * 128;

    const int lr = tid >> 2;          // 0..63
    const int lc = (tid & 3) * 4;     // 0,4,8,12

    const float* Aeff = QKV ? Ain : (const float*)g_ctx;
    const float* Ap = Aeff + (size_t)(m0 + lr) * K + lc;
    const float* Wp = W    + (size_t)(n0 + lr) * K + lc;

    float acc[4][4][4];
#pragma unroll
    for (int mi = 0; mi < 4; ++mi)
#pragma unroll
        for (int ni = 0; ni < 4; ++ni)
#pragma unroll
            for (int r = 0; r < 4; ++r) acc[mi][ni][r] = 0.f;

    const int nIter = K / 16;

    float4 pa0, pa1, pb0, pb1;
    pa0 = *(const float4*)(Ap);
    pa1 = *(const float4*)(Ap + (size_t)64 * K);
    pb0 = *(const float4*)(Wp);
    pb1 = *(const float4*)(Wp + (size_t)64 * K);

    // store tile 0 -> buf 0
    {
        float4 c0 = {ftf32(pa0.x), ftf32(pa0.y), ftf32(pa0.z), ftf32(pa0.w)};
        float4 c1 = {ftf32(pa1.x), ftf32(pa1.y), ftf32(pa1.z), ftf32(pa1.w)};
        *(float4*)&As[0][lr * 20 + lc]        = c0;
        *(float4*)&As[0][(lr + 64) * 20 + lc] = c1;
        float4 d0 = {ftf32(pb0.x), ftf32(pb0.y), ftf32(pb0.z), ftf32(pb0.w)};
        float4 d1 = {ftf32(pb1.x), ftf32(pb1.y), ftf32(pb1.z), ftf32(pb1.w)};
        *(float4*)&Bs[0][lr * 20 + lc]        = d0;
        *(float4*)&Bs[0][(lr + 64) * 20 + lc] = d1;
    }
    __syncthreads();

    for (int it = 0; it < nIter; ++it) {
        const int cur = it & 1;
        if (it + 1 < nIter) {
            const int k0 = (it + 1) * 16;
            pa0 = *(const float4*)(Ap + k0);
            pa1 = *(const float4*)(Ap + (size_t)64 * K + k0);
            pb0 = *(const float4*)(Wp + k0);
            pb1 = *(const float4*)(Wp + (size_t)64 * K + k0);
            const int nxt = cur ^ 1;
            float4 c0 = {ftf32(pa0.x), ftf32(pa0.y), ftf32(pa0.z), ftf32(pa0.w)};
            float4 c1 = {ftf32(pa1.x), ftf32(pa1.y), ftf32(pa1.z), ftf32(pa1.w)};
            *(float4*)&As[nxt][lr * 20 + lc]        = c0;
            *(float4*)&As[nxt][(lr + 64) * 20 + lc] = c1;
            float4 d0 = {ftf32(pb0.x), ftf32(pb0.y), ftf32(pb0.z), ftf32(pb0.w)};
            float4 d1 = {ftf32(pb1.x), ftf32(pb1.y), ftf32(pb1.z), ftf32(pb1.w)};
            *(float4*)&Bs[nxt][lr * 20 + lc]        = d0;
            *(float4*)&Bs[nxt][(lr + 64) * 20 + lc] = d1;
        }

        const float* as = As[cur];
        const float* bs = Bs[cur];
#pragma unroll
        for (int ks = 0; ks < 2; ++ks) {
            const int ko = ks * 8;
            uint32_t af[4][4];
#pragma unroll
            for (int mi = 0; mi < 4; ++mi) {
                const int r = wm * 64 + mi * 16 + gid;
                af[mi][0] = __float_as_uint(as[r * 20 + ko + tg]);
                af[mi][1] = __float_as_uint(as[(r + 8) * 20 + ko + tg]);
                af[mi][2] = __float_as_uint(as[r * 20 + ko + tg + 4]);
                af[mi][3] = __float_as_uint(as[(r + 8) * 20 + ko + tg + 4]);
            }
            uint32_t bf[4][2];
#pragma unroll
            for (int ni = 0; ni < 4; ++ni) {
                const int n = wn * 32 + ni * 8 + gid;
                bf[ni][0] = __float_as_uint(bs[n * 20 + ko + tg]);
                bf[ni][1] = __float_as_uint(bs[n * 20 + ko + tg + 4]);
            }
#pragma unroll
            for (int mi = 0; mi < 4; ++mi)
#pragma unroll
                for (int ni = 0; ni < 4; ++ni)
                    mma_tf32(acc[mi][ni], af[mi], bf[ni]);
        }
        __syncthreads();
    }

    float sig = 0.f;
    if (QKV) sig = 1.f / (1.f + __expf(-temp[0]));

#pragma unroll
    for (int mi = 0; mi < 4; ++mi) {
#pragma unroll
        for (int ni = 0; ni < 4; ++ni) {
            const int rbase = m0 + wm * 64 + mi * 16 + gid;
            const int col   = n0 + wn * 32 + ni * 8 + 2 * tg;
#pragma unroll
            for (int e = 0; e < 4; ++e) {
                const int m = rbase + (e >> 1) * 8;
                const int c = col + (e & 1);
                const float val = acc[mi][ni][e] + bias[c];
                if (QKV) {
                    const int bb = m >> 11;
                    const int nn = m & (N_ - 1);
                    const int which = c >> 10;       // 0=q 1=k 2=v
                    const int rem = c & 1023;
                    const int h = rem >> 6;
                    const int d = rem & 63;
                    const size_t idx = ((size_t)((bb * H_ + h) * N_) + nn) * DH_ + d;
                    if (which == 0)      g_q[idx] = val + eps[idx] * sig;
                    else if (which == 1) g_k[idx] = val;
                    else                 g_v[idx] = val;
                } else {
                    C[(size_t)m * Nout + c] = val;
                }
            }
        }
    }
}

// ---------------------------------------------------------------------------
// Flash-attention, tf32 tensor cores. Block = (bh, 128-query tile), 256 thr.
// Warp w owns query rows [w*16, w*16+16) -> softmax is quad-shuffle local.
// Smem stride 68 -> all fragment LDS conflict-free (bank == lane).
// ---------------------------------------------------------------------------
__global__ __launch_bounds__(256) void attn_tc()
{
    extern __shared__ float sm[];
    float* Qs = sm;                  // 128 x 68  [q][dh]
    float* Ks = Qs + 128 * 68;       // 64 x 68   [key][dh]
    float* Vs = Ks + 64 * 68;        // 64 x 68   [dh][key]  (transposed)
    float* Ps = Vs + 64 * 68;        // 128 x 68  [q][key]

    const int bh = blockIdx.x;
    const int b  = bh >> 4;
    const int h  = bh & 15;
    const int q0 = blockIdx.y * 128;
    const int tid  = threadIdx.x;
    const int wid  = tid >> 5;
    const int lane = tid & 31;
    const int gid  = lane >> 2;
    const int tg   = lane & 3;

    const size_t head_off = (size_t)(b * H_ + h) * N_ * DH_;
    const float* qbase = g_q + head_off;
    const float* kbase = g_k + head_off;
    const float* vbase = g_v + head_off;

    const float scale = 0.125f;   // 1/sqrt(64)

    // Load Q tile: scale + round-to-tf32
    for (int idx = tid; idx < 128 * 16; idx += 256) {
        const int r = idx >> 4, c4 = (idx & 15) * 4;
        float4 t = *(const float4*)(qbase + (size_t)(q0 + r) * DH_ + c4);
        float4 o4 = {ftf32(t.x * scale), ftf32(t.y * scale),
                     ftf32(t.z * scale), ftf32(t.w * scale)};
        *(float4*)&Qs[r * 68 + c4] = o4;
    }

    float oacc[8][4];
#pragma unroll
    for (int ni = 0; ni < 8; ++ni)
#pragma unroll
        for (int r = 0; r < 4; ++r) oacc[ni][r] = 0.f;
    float mst0 = -INFINITY, mst1 = -INFINITY;
    float lst0 = 0.f, lst1 = 0.f;

    const int r0 = wid * 16 + gid;   // this thread's row pair: r0, r0+8

    for (int kt = 0; kt < N_ / 64; ++kt) {
        const int k0 = kt * 64;
        __syncthreads();   // prior iteration's readers of Ks/Vs done (covers Q store too)

        // K tile [key][dh]
        for (int idx = tid; idx < 64 * 16; idx += 256) {
            const int r = idx >> 4, c4 = (idx & 15) * 4;
            float4 t = *(const float4*)(kbase + (size_t)(k0 + r) * DH_ + c4);
            float4 o4 = {ftf32(t.x), ftf32(t.y), ftf32(t.z), ftf32(t.w)};
            *(float4*)&Ks[r * 68 + c4] = o4;
        }
        // V tile transposed [dh][key]
        for (int idx = tid; idx < 64 * 16; idx += 256) {
            const int r = idx >> 4, c4 = (idx & 15) * 4;
            float4 t = *(const float4*)(vbase + (size_t)(k0 + r) * DH_ + c4);
            Vs[(c4 + 0) * 68 + r] = ftf32(t.x);
            Vs[(c4 + 1) * 68 + r] = ftf32(t.y);
            Vs[(c4 + 2) * 68 + r] = ftf32(t.z);
            Vs[(c4 + 3) * 68 + r] = ftf32(t.w);
        }
        __syncthreads();

        // S = Q @ K^T : warp tile 16 x 64 (8 n-frags), K=64 (8 k-steps)
        float s[8][4];
#pragma unroll
        for (int ni = 0; ni < 8; ++ni)
#pragma unroll
            for (int r = 0; r < 4; ++r) s[ni][r] = 0.f;

#pragma unroll
        for (int ks = 0; ks < 8; ++ks) {
            const int ko = ks * 8;
            uint32_t af[4];
            af[0] = __float_as_uint(Qs[r0 * 68 + ko + tg]);
            af[1] = __float_as_uint(Qs[(r0 + 8) * 68 + ko + tg]);
            af[2] = __float_as_uint(Qs[r0 * 68 + ko + tg + 4]);
            af[3] = __float_as_uint(Qs[(r0 + 8) * 68 + ko + tg + 4]);
#pragma unroll
            for (int ni = 0; ni < 8; ++ni) {
                const int n = ni * 8 + gid;
                uint32_t bf[2];
                bf[0] = __float_as_uint(Ks[n * 68 + ko + tg]);
                bf[1] = __float_as_uint(Ks[n * 68 + ko + tg + 4]);
                mma_tf32(s[ni], af, bf);
            }
        }

        // Online softmax. Row r0: regs 0,1 ; row r0+8: regs 2,3. Quad reduce.
        float mx0 = -INFINITY, mx1 = -INFINITY;
#pragma unroll
        for (int ni = 0; ni < 8; ++ni) {
            mx0 = fmaxf(mx0, fmaxf(s[ni][0], s[ni][1]));
            mx1 = fmaxf(mx1, fmaxf(s[ni][2], s[ni][3]));
        }
        mx0 = fmaxf(mx0, __shfl_xor_sync(0xffffffffu, mx0, 1));
        mx0 = fmaxf(mx0, __shfl_xor_sync(0xffffffffu, mx0, 2));
        mx1 = fmaxf(mx1, __shfl_xor_sync(0xffffffffu, mx1, 1));
        mx1 = fmaxf(mx1, __shfl_xor_sync(0xffffffffu, mx1, 2));

        const float nm0 = fmaxf(mst0, mx0);
        const float nm1 = fmaxf(mst1, mx1);
        const float corr0 = __expf(mst0 - nm0);
        const float corr1 = __expf(mst1 - nm1);
        mst0 = nm0; mst1 = nm1;

        float rs0 = 0.f, rs1 = 0.f;
        float p[8][4];
#pragma unroll
        for (int ni = 0; ni < 8; ++ni) {
            p[ni][0] = __expf(s[ni][0] - nm0);
            p[ni][1] = __expf(s[ni][1] - nm0);
            p[ni][2] = __expf(s[ni][2] - nm1);
            p[ni][3] = __expf(s[ni][3] - nm1);
            rs0 += p[ni][0] + p[ni][1];
            rs1 += p[ni][2] + p[ni][3];
        }
        rs0 += __shfl_xor_sync(0xffffffffu, rs0, 1);
        rs0 += __shfl_xor_sync(0xffffffffu, rs0, 2);
        rs1 += __shfl_xor_sync(0xffffffffu, rs1, 1);
        rs1 += __shfl_xor_sync(0xffffffffu, rs1, 2);
        lst0 = lst0 * corr0 + rs0;
        lst1 = lst1 * corr1 + rs1;
#pragma unroll
        for (int ni = 0; ni < 8; ++ni) {
            oacc[ni][0] *= corr0; oacc[ni][1] *= corr0;
            oacc[ni][2] *= corr1; oacc[ni][3] *= corr1;
        }

        // Write P to smem (warp-local rows -> only syncwarp needed)
#pragma unroll
        for (int ni = 0; ni < 8; ++ni) {
            const int c = ni * 8 + 2 * tg;
            float2 v0 = {ftf32(p[ni][0]), ftf32(p[ni][1])};
            float2 v1 = {ftf32(p[ni][2]), ftf32(p[ni][3])};
            *(float2*)&Ps[r0 * 68 + c]       = v0;
            *(float2*)&Ps[(r0 + 8) * 68 + c] = v1;
        }
        __syncwarp();

        // O += P @ V : k over 64 keys, n over 64 dh
#pragma unroll
        for (int ks = 0; ks < 8; ++ks) {
            const int ko = ks * 8;
            uint32_t af[4];
            af[0] = __float_as_uint(Ps[r0 * 68 + ko + tg]);
            af[1] = __float_as_uint(Ps[(r0 + 8) * 68 + ko + tg]);
            af[2] = __float_as_uint(Ps[r0 * 68 + ko + tg + 4]);
            af[3] = __float_as_uint(Ps[(r0 + 8) * 68 + ko + tg + 4]);
#pragma unroll
            for (int ni = 0; ni < 8; ++ni) {
                const int n = ni * 8 + gid;
                uint32_t bf[2];
                bf[0] = __float_as_uint(Vs[n * 68 + ko + tg]);
                bf[1] = __float_as_uint(Vs[n * 68 + ko + tg + 4]);
                mma_tf32(oacc[ni], af, bf);
            }
        }
    }

    // Normalize, write context [B,N,DIM]
    const float inv0 = 1.f / lst0;
    const float inv1 = 1.f / lst1;
    const size_t row0 = (size_t)(b * N_ + q0 + r0) * DIM_ + h * DH_;
    const size_t row1 = (size_t)(b * N_ + q0 + r0 + 8) * DIM_ + h * DH_;
#pragma unroll
    for (int ni = 0; ni < 8; ++ni) {
        const int c = ni * 8 + 2 * tg;
        float2 v0 = {oacc[ni][0] * inv0, oacc[ni][1] * inv0};
        float2 v1 = {oacc[ni][2] * inv1, oacc[ni][3] * inv1};
        *(float2*)&g_ctx[row0 + c] = v0;
        *(float2*)&g_ctx[row1 + c] = v1;
    }
}

// ---------------------------------------------------------------------------
extern "C" void kernel_launch(void* const* d_in, const int* in_sizes, int n_in,
                              void* d_out, int out_size)
{
    const float* x      = (const float*)d_in[0];
    const float* qkv_w  = (const float*)d_in[1];
    const float* qkv_b  = (const float*)d_in[2];
    const float* proj_w = (const float*)d_in[3];
    const float* proj_b = (const float*)d_in[4];
    const float* temp   = (const float*)d_in[5];
    const float* eps    = (const float*)d_in[6];
    float* out = (float*)d_out;

    const int ATTN_SMEM = (128 * 68 + 64 * 68 + 64 * 68 + 128 * 68) * 4;  // 104448
    cudaFuncSetAttribute(attn_tc, cudaFuncAttributeMaxDynamicSharedMemorySize, ATTN_SMEM);

    dim3 gA(3 * DIM_ / 128, (B_ * N_) / 128);   // (24, 64)
    gemm_tc<true><<<gA, 256>>>(x, qkv_w, qkv_b, nullptr, 3 * DIM_, DIM_, eps, temp);

    dim3 gAtt(B_ * H_, N_ / 128);               // (64, 16)
    attn_tc<<<gAtt, 256, ATTN_SMEM>>>();

    dim3 gC(DIM_ / 128, (B_ * N_) / 128);       // (8, 64)
    gemm_tc<false><<<gC, 256>>>(nullptr, proj_w, proj_b, out, DIM_, DIM_, nullptr, nullptr);
}